// round 16
// baseline (speedup 1.0000x reference)
#include <cuda_runtime.h>
#include <cstdint>
#include <math.h>

// Problem constants (B=2, S=2048, D=2048, H=16, hd=128)
#define B_    2
#define S_    2048
#define D_    2048
#define H_    16
#define HD_   128
#define MTOK  (B_ * S_)   // 4096 token rows

// ---------------- scratch (static device globals; no allocation) -------------
__device__ float g_q[(size_t)B_ * S_ * D_];
__device__ float g_k[(size_t)B_ * S_ * D_];
__device__ float g_v[(size_t)B_ * S_ * D_];
__device__ float g_ctx[(size_t)B_ * S_ * D_];
__device__ float g_xr[(size_t)B_ * S_ * D_];      // tf32-rounded x
__device__ float g_wqr[(size_t)D_ * D_];          // tf32-rounded weights
__device__ float g_wkr[(size_t)D_ * D_];
__device__ float g_wvr[(size_t)D_ * D_];
__device__ float g_wor[(size_t)D_ * D_];

// ---------------- helpers ----------------------------------------------------
__device__ __forceinline__ uint32_t f2tf32(float f) {
    uint32_t r;
    asm("cvt.rna.tf32.f32 %0, %1;" : "=r"(r) : "f"(f));
    return r;
}
__device__ __forceinline__ void mma_tf32(float* d, const uint32_t* a, const uint32_t* b) {
    asm volatile(
        "mma.sync.aligned.m16n8k8.row.col.f32.tf32.tf32.f32 "
        "{%0,%1,%2,%3}, {%4,%5,%6,%7}, {%8,%9}, {%0,%1,%2,%3};\n"
        : "+f"(d[0]), "+f"(d[1]), "+f"(d[2]), "+f"(d[3])
        : "r"(a[0]), "r"(a[1]), "r"(a[2]), "r"(a[3]), "r"(b[0]), "r"(b[1]));
}
__device__ __forceinline__ void cp16(uint32_t saddr, const void* gptr) {
    asm volatile("cp.async.cg.shared.global [%0], [%1], 16;\n"
                 :: "r"(saddr), "l"(gptr));
}
__device__ __forceinline__ void cp_commit() {
    asm volatile("cp.async.commit_group;\n");
}
template <int N>
__device__ __forceinline__ void cp_wait_group() {
    asm volatile("cp.async.wait_group %0;\n" :: "n"(N));
}

// ============================================================================
// Pre-round: out[i] = tf32_rna(in[i]) stored as fp32 bits (low 13 bits zero).
// ============================================================================
__global__ __launch_bounds__(256) void round_tf32_kernel(
    const float4* __restrict__ in, float4* __restrict__ out, int n4)
{
    int stride = gridDim.x * blockDim.x;
    for (int i = blockIdx.x * blockDim.x + threadIdx.x; i < n4; i += stride) {
        float4 v = in[i];
        float4 r;
        r.x = __uint_as_float(f2tf32(v.x));
        r.y = __uint_as_float(f2tf32(v.y));
        r.z = __uint_as_float(f2tf32(v.z));
        r.w = __uint_as_float(f2tf32(v.w));
        out[i] = r;
    }
}

// ============================================================================
// GEMM v5: Y[M,N] = A[M,K] @ W[N,K]^T, inputs pre-rounded tf32.
// One 512-thread CTA (16 warps, 4m x 4n of 64x32 warp tiles), block tile
// 256(m) x 128(n) x 64(k). Double-buffered cp.async, prefetch before compute,
// one __syncthreads per 64-k block (32 total). smem 208.9KB, ~127 regs.
// blockIdx.z in {0,1,2} selects weight/output (merged QKV launch).
// ============================================================================
#define GM 256
#define GN 128
#define GK 64
#define GS 68    // row stride words (68 % 32 == 4 -> frag bank 4g+t, conflict-free)
#define ATILE (GM * GS)                          // 17408 words
#define BTILE (GN * GS)                          // 8704 words
#define G_SMEM_WORDS (2 * (ATILE + BTILE))       // 52224
#define G_SMEM_BYTES (G_SMEM_WORDS * 4)          // 208896

template <bool ROUND_OUT>
__global__ __launch_bounds__(512, 1) void gemm_v5(
    const float* __restrict__ A,
    const float* __restrict__ W0, const float* __restrict__ W1,
    const float* __restrict__ W2,
    float* __restrict__ Y0, float* __restrict__ Y1, float* __restrict__ Y2)
{
    const float* __restrict__ W = (blockIdx.z == 0) ? W0 : (blockIdx.z == 1 ? W1 : W2);
    float* __restrict__ Y       = (blockIdx.z == 0) ? Y0 : (blockIdx.z == 1 ? Y1 : Y2);

    extern __shared__ uint32_t gsm[];
    uint32_t* sA = gsm;                     // [2][ATILE]
    uint32_t* sB = gsm + 2 * ATILE;         // [2][BTILE]
    const uint32_t sA_u = (uint32_t)__cvta_generic_to_shared(sA);
    const uint32_t sB_u = (uint32_t)__cvta_generic_to_shared(sB);

    const int tid  = threadIdx.x;
    const int lane = tid & 31;
    const int warp = tid >> 5;
    const int g = lane >> 2, t = lane & 3;
    const int wm = warp >> 2;               // 0..3 -> 64-row slab
    const int wn = warp & 3;                // 0..3 -> 32-col slab
    const int bm0 = blockIdx.y * GM;
    const int bn0 = blockIdx.x * GN;

    float acc[4][4][4];
#pragma unroll
    for (int mi = 0; mi < 4; mi++)
#pragma unroll
        for (int ni = 0; ni < 4; ni++)
#pragma unroll
            for (int j = 0; j < 4; j++) acc[mi][ni][j] = 0.f;

    // fill one 64-k block: A 4096 chunks (8/thr), B 2048 chunks (4/thr)
    auto fill = [&](int b, int kf) {
        const uint32_t ab = sA_u + (uint32_t)(b * ATILE * 4);
        const uint32_t bb = sB_u + (uint32_t)(b * BTILE * 4);
#pragma unroll
        for (int i = 0; i < 8; i++) {
            int idx = tid + i * 512;         // 0..4095
            int r = idx >> 4;                // 0..255
            int c = (idx & 15) << 2;         // 0..60
            cp16(ab + (uint32_t)((r * GS + c) * 4),
                 A + (size_t)(bm0 + r) * D_ + kf + c);
        }
#pragma unroll
        for (int i = 0; i < 4; i++) {
            int idx = tid + i * 512;         // 0..2047
            int r = idx >> 4;                // 0..127
            int c = (idx & 15) << 2;
            cp16(bb + (uint32_t)((r * GS + c) * 4),
                 W + (size_t)(bn0 + r) * D_ + kf + c);
        }
    };

    fill(0, 0);
    cp_commit();

    const int NB = D_ / GK;   // 32
    for (int j = 0; j < NB; j++) {
        cp_wait_group<0>();
        __syncthreads();                 // buffer j&1 ready

        if (j + 1 < NB) {                // prefetch BEFORE compute
            fill((j + 1) & 1, (j + 1) * GK);
            cp_commit();
        }

        const uint32_t* cA = sA + (j & 1) * ATILE;
        const uint32_t* cB = sB + (j & 1) * BTILE;
#pragma unroll
        for (int ks = 0; ks < GK; ks += 8) {
            uint32_t af[4][4], bf[4][2];
#pragma unroll
            for (int mi = 0; mi < 4; mi++) {
                int r0 = wm * 64 + mi * 16;
                af[mi][0] = cA[(r0 + g    ) * GS + ks + t    ];
                af[mi][1] = cA[(r0 + g + 8) * GS + ks + t    ];
                af[mi][2] = cA[(r0 + g    ) * GS + ks + t + 4];
                af[mi][3] = cA[(r0 + g + 8) * GS + ks + t + 4];
            }
#pragma unroll
            for (int ni = 0; ni < 4; ni++) {
                int c0 = wn * 32 + ni * 8;
                bf[ni][0] = cB[(c0 + g) * GS + ks + t    ];
                bf[ni][1] = cB[(c0 + g) * GS + ks + t + 4];
            }
#pragma unroll
            for (int mi = 0; mi < 4; mi++)
#pragma unroll
                for (int ni = 0; ni < 4; ni++)
                    mma_tf32(acc[mi][ni], af[mi], bf[ni]);
        }
    }

    // ---- epilogue ----
#pragma unroll
    for (int mi = 0; mi < 4; mi++)
#pragma unroll
        for (int ni = 0; ni < 4; ni++) {
            int r0 = bm0 + wm * 64 + mi * 16 + g;
            int c0 = bn0 + wn * 32 + ni * 8 + 2 * t;
            float v0 = acc[mi][ni][0], v1 = acc[mi][ni][1];
            float v2 = acc[mi][ni][2], v3 = acc[mi][ni][3];
            if (ROUND_OUT) {
                v0 = __uint_as_float(f2tf32(v0));
                v1 = __uint_as_float(f2tf32(v1));
                v2 = __uint_as_float(f2tf32(v2));
                v3 = __uint_as_float(f2tf32(v3));
            }
            *(float2*)&Y[(size_t)r0 * D_ + c0] = make_float2(v0, v1);
            *(float2*)&Y[(size_t)(r0 + 8) * D_ + c0] = make_float2(v2, v3);
        }
}

// ============================================================================
// Flash attention v3: FQ=64, 4 warps (128 threads), 2 CTAs/SM.
//   Q held in REGISTERS (loaded once; q is pre-rounded tf32 -> raw bits).
//   K,V single-buffered in smem, cp.async overlapped:
//     V[i] copies during QK; K[i+1] copies during softmax+PV.
//   Per-row arithmetic order identical to R14 -> identical rel_err.
// smem: K 64x132 | V 64x136 | P 64x68 = 86016 B -> 2 CTAs/SM (172KB).
// ============================================================================
#define FQ   64
#define FKV  64
#define SQW  132
#define SVW  136
#define SPW  68
#define KOFF 0
#define VOFF (FKV * SQW)                // 8448
#define POFF (VOFF + FKV * SVW)         // 17152
#define FSMEM_WORDS (POFF + FQ * SPW)   // 21504
#define FSMEM_BYTES (FSMEM_WORDS * 4)   // 86016 B

__global__ __launch_bounds__(128) void flash_v3(
    const float* __restrict__ Q, const float* __restrict__ Kg,
    const float* __restrict__ Vg, float* __restrict__ O)
{
    extern __shared__ uint32_t sm[];
    const uint32_t sm_u = (uint32_t)__cvta_generic_to_shared(sm);
    const int tid  = threadIdx.x;
    const int lane = tid & 31;
    const int w    = tid >> 5;           // 0..3
    const int g = lane >> 2, t = lane & 3;
    const int qt = blockIdx.x, h = blockIdx.y, b = blockIdx.z;
    const int wr = w * 16;

    const size_t qbase  = ((size_t)(b * S_ + qt * FQ)) * D_ + (size_t)h * HD_;
    const size_t kvbase = ((size_t)b * S_) * D_ + (size_t)h * HD_;

    // copy helpers: tile 64x128 floats = 2048 16B-chunks, 16 per thread
    auto copy_tile = [&](int dst_words, int stride, const float* src) {
#pragma unroll
        for (int i = 0; i < 16; i++) {
            int idx = tid + i * 128;         // 0..2047
            int r = idx >> 5;                // 0..63
            int c = (idx & 31) << 2;         // 0..124
            cp16(sm_u + (uint32_t)((dst_words + r * stride + c) * 4),
                 src + (size_t)r * D_ + c);
        }
    };

    // prologue: K[0] then V[0] as separate commit groups
    copy_tile(KOFF, SQW, Kg + kvbase);
    cp_commit();
    copy_tile(VOFF, SVW, Vg + kvbase);
    cp_commit();

    // Q fragments in registers (q pre-rounded tf32; raw bits feed mma)
    uint32_t qf[16][4];
    {
        const float* Qw = Q + qbase;
#pragma unroll
        for (int ks16 = 0; ks16 < 16; ks16++) {
            int c = ks16 * 8;
            qf[ks16][0] = __float_as_uint(Qw[(size_t)(wr + g    ) * D_ + c + t    ]);
            qf[ks16][1] = __float_as_uint(Qw[(size_t)(wr + g + 8) * D_ + c + t    ]);
            qf[ks16][2] = __float_as_uint(Qw[(size_t)(wr + g    ) * D_ + c + t + 4]);
            qf[ks16][3] = __float_as_uint(Qw[(size_t)(wr + g + 8) * D_ + c + t + 4]);
        }
    }

    float o[16][4];
#pragma unroll
    for (int ni = 0; ni < 16; ni++)
#pragma unroll
        for (int j = 0; j < 4; j++) o[ni][j] = 0.f;
    float m0 = -1e30f, m1 = -1e30f, l0 = 0.f, l1 = 0.f;
    const float scale = 0.08838834764831845f;   // 1/sqrt(128)

    cp_wait_group<0>();
    __syncthreads();                      // K[0], V[0] visible

    const int NT = S_ / FKV;              // 32 tiles
    for (int it = 0; it < NT; it++) {
        const int kv0 = it * FKV;

        // ---- S = Q @ K^T (Q from regs, K from smem) ----
        float s[8][4];
#pragma unroll
        for (int ni = 0; ni < 8; ni++)
#pragma unroll
            for (int j = 0; j < 4; j++) s[ni][j] = 0.f;

#pragma unroll
        for (int ks16 = 0; ks16 < 16; ks16++) {
            int ks = ks16 * 8;
#pragma unroll
            for (int ni = 0; ni < 8; ni++) {
                uint32_t bf[2];
                bf[0] = sm[KOFF + (ni * 8 + g) * SQW + ks + t    ];
                bf[1] = sm[KOFF + (ni * 8 + g) * SQW + ks + t + 4];
                mma_tf32(s[ni], qf[ks16], bf);
            }
        }
        __syncthreads();                 // all warps done reading K[it]

        // ---- issue K[it+1] (overlaps softmax + PV) ----
        if (it + 1 < NT) {
            copy_tile(KOFF, SQW, Kg + kvbase + (size_t)(kv0 + FKV) * D_);
        }
        cp_commit();

        // ---- online softmax (numerics identical to R14) ----
        float mx0 = -1e30f, mx1 = -1e30f;
#pragma unroll
        for (int ni = 0; ni < 8; ni++) {
#pragma unroll
            for (int j = 0; j < 4; j++) s[ni][j] *= scale;
            mx0 = fmaxf(mx0, fmaxf(s[ni][0], s[ni][1]));
            mx1 = fmaxf(mx1, fmaxf(s[ni][2], s[ni][3]));
        }
        mx0 = fmaxf(mx0, __shfl_xor_sync(0xffffffffu, mx0, 1));
        mx0 = fmaxf(mx0, __shfl_xor_sync(0xffffffffu, mx0, 2));
        mx1 = fmaxf(mx1, __shfl_xor_sync(0xffffffffu, mx1, 1));
        mx1 = fmaxf(mx1, __shfl_xor_sync(0xffffffffu, mx1, 2));
        float mn0 = fmaxf(m0, mx0), mn1 = fmaxf(m1, mx1);
        float a0 = __expf(m0 - mn0), a1 = __expf(m1 - mn1);
        m0 = mn0; m1 = mn1;

        float r0 = 0.f, r1 = 0.f;
#pragma unroll
        for (int ni = 0; ni < 8; ni++) {
            float p0 = __expf(s[ni][0] - mn0);
            float p1 = __expf(s[ni][1] - mn0);
            float p2 = __expf(s[ni][2] - mn1);
            float p3 = __expf(s[ni][3] - mn1);
            r0 += p0 + p1; r1 += p2 + p3;
            uint2 u01 = make_uint2(f2tf32(p0), f2tf32(p1));
            uint2 u23 = make_uint2(f2tf32(p2), f2tf32(p3));
            *(uint2*)&sm[POFF + (wr + g    ) * SPW + ni * 8 + 2 * t] = u01;
            *(uint2*)&sm[POFF + (wr + g + 8) * SPW + ni * 8 + 2 * t] = u23;
        }
        r0 += __shfl_xor_sync(0xffffffffu, r0, 1);
        r0 += __shfl_xor_sync(0xffffffffu, r0, 2);
        r1 += __shfl_xor_sync(0xffffffffu, r1, 1);
        r1 += __shfl_xor_sync(0xffffffffu, r1, 2);
        l0 = l0 * a0 + r0;
        l1 = l1 * a1 + r1;
#pragma unroll
        for (int ni = 0; ni < 16; ni++) {
            o[ni][0] *= a0; o[ni][1] *= a0; o[ni][2] *= a1; o[ni][3] *= a1;
        }

        cp_wait_group<1>();    // V[it] landed (K[it+1] may still fly)
        __syncthreads();       // V visible to all; P stores (warp-private) done

        // ---- O += P @ V ----
#pragma unroll
        for (int ks = 0; ks < FKV; ks += 8) {
            uint32_t af[4];
            af[0] = sm[POFF + (wr + g    ) * SPW + ks + t    ];
            af[1] = sm[POFF + (wr + g + 8) * SPW + ks + t    ];
            af[2] = sm[POFF + (wr + g    ) * SPW + ks + t + 4];
            af[3] = sm[POFF + (wr + g + 8) * SPW + ks + t + 4];
#pragma unroll
            for (int ni = 0; ni < 16; ni++) {
                uint32_t bf[2];
                bf[0] = sm[VOFF + (ks + t    ) * SVW + ni * 8 + g];
                bf[1] = sm[VOFF + (ks + t + 4) * SVW + ni * 8 + g];
                mma_tf32(o[ni], af, bf);
            }
        }
        __syncthreads();       // all warps done reading V[it]

        // ---- issue V[it+1] (overlaps next QK) ----
        if (it + 1 < NT) {
            copy_tile(VOFF, SVW, Vg + kvbase + (size_t)(kv0 + FKV) * D_);
        }
        cp_commit();
        cp_wait_group<1>();    // K[it+1] landed (V[it+1] may still fly)
        __syncthreads();
    }

    // epilogue: normalize + tf32-round (GEMM2 consumes raw)
    float i0 = 1.0f / l0;
    float i1 = 1.0f / l1;
#pragma unroll
    for (int ni = 0; ni < 16; ni++) {
        int c0 = ni * 8 + 2 * t;
        *(float2*)&O[qbase + (size_t)(wr + g) * D_ + c0] = make_float2(
            __uint_as_float(f2tf32(o[ni][0] * i0)),
            __uint_as_float(f2tf32(o[ni][1] * i0)));
        *(float2*)&O[qbase + (size_t)(wr + g + 8) * D_ + c0] = make_float2(
            __uint_as_float(f2tf32(o[ni][2] * i1)),
            __uint_as_float(f2tf32(o[ni][3] * i1)));
    }
}

// ============================================================================
// Launch: pre-round, merged q/k/v projections, flash, out projection
// ============================================================================
extern "C" void kernel_launch(void* const* d_in, const int* in_sizes, int n_in,
                              void* d_out, int out_size) {
    const float* x  = (const float*)d_in[0];
    const float* wq = (const float*)d_in[1];
    const float* wk = (const float*)d_in[2];
    const float* wv = (const float*)d_in[3];
    const float* wo = (const float*)d_in[4];
    float* out = (float*)d_out;

    float *qb, *kb, *vb, *cb, *xr, *wqr, *wkr, *wvr, *wor;
    cudaGetSymbolAddress((void**)&qb, g_q);
    cudaGetSymbolAddress((void**)&kb, g_k);
    cudaGetSymbolAddress((void**)&vb, g_v);
    cudaGetSymbolAddress((void**)&cb, g_ctx);
    cudaGetSymbolAddress((void**)&xr, g_xr);
    cudaGetSymbolAddress((void**)&wqr, g_wqr);
    cudaGetSymbolAddress((void**)&wkr, g_wkr);
    cudaGetSymbolAddress((void**)&wvr, g_wvr);
    cudaGetSymbolAddress((void**)&wor, g_wor);

    cudaFuncSetAttribute(gemm_v5<true>,
                         cudaFuncAttributeMaxDynamicSharedMemorySize, G_SMEM_BYTES);
    cudaFuncSetAttribute(gemm_v5<false>,
                         cudaFuncAttributeMaxDynamicSharedMemorySize, G_SMEM_BYTES);
    cudaFuncSetAttribute(flash_v3,
                         cudaFuncAttributeMaxDynamicSharedMemorySize, FSMEM_BYTES);

    // ---- pre-round inputs to tf32 (stored as fp32 bits) ----
    const int nblk = 1184;   // 8 * 148
    const int n4x = (MTOK * D_) / 4;
    const int n4w = (D_ * D_) / 4;
    round_tf32_kernel<<<nblk, 256>>>((const float4*)x,  (float4*)xr,  n4x);
    round_tf32_kernel<<<nblk, 256>>>((const float4*)wq, (float4*)wqr, n4w);
    round_tf32_kernel<<<nblk, 256>>>((const float4*)wk, (float4*)wkr, n4w);
    round_tf32_kernel<<<nblk, 256>>>((const float4*)wv, (float4*)wvr, n4w);
    round_tf32_kernel<<<nblk, 256>>>((const float4*)wo, (float4*)wor, n4w);

    // ---- q/k/v projections (merged), outputs tf32-rounded ----
    dim3 gqkv(D_ / GN, MTOK / GM, 3);   // (16, 16, 3)
    gemm_v5<true><<<gqkv, 512, G_SMEM_BYTES>>>(xr, wqr, wkr, wvr, qb, kb, vb);

    // ---- attention (ctx written tf32-rounded), 2 CTAs/SM ----
    flash_v3<<<dim3(S_ / FQ, H_, B_), 128, FSMEM_BYTES>>>(qb, kb, vb, cb);

    // ---- output projection, unrounded final result ----
    dim3 go(D_ / GN, MTOK / GM, 1);     // (16, 16, 1)
    gemm_v5<false><<<go, 512, G_SMEM_BYTES>>>(cb, wor, wor, wor, out, out, out);
}

// round 17
// speedup vs baseline: 1.0795x; 1.0795x over previous
#include <cuda_runtime.h>
#include <cstdint>
#include <math.h>

// Problem constants (B=2, S=2048, D=2048, H=16, hd=128)
#define B_    2
#define S_    2048
#define D_    2048
#define H_    16
#define HD_   128
#define MTOK  (B_ * S_)   // 4096 token rows

// ---------------- scratch (static device globals; no allocation) -------------
__device__ float g_q[(size_t)B_ * S_ * D_];
__device__ float g_k[(size_t)B_ * S_ * D_];
__device__ float g_v[(size_t)B_ * S_ * D_];
__device__ float g_ctx[(size_t)B_ * S_ * D_];
__device__ float g_xr[(size_t)B_ * S_ * D_];      // tf32-rounded x
__device__ float g_wqr[(size_t)D_ * D_];          // tf32-rounded weights
__device__ float g_wkr[(size_t)D_ * D_];
__device__ float g_wvr[(size_t)D_ * D_];
__device__ float g_wor[(size_t)D_ * D_];

// ---------------- helpers ----------------------------------------------------
__device__ __forceinline__ uint32_t f2tf32(float f) {
    uint32_t r;
    asm("cvt.rna.tf32.f32 %0, %1;" : "=r"(r) : "f"(f));
    return r;
}
__device__ __forceinline__ void mma_tf32(float* d, const uint32_t* a, const uint32_t* b) {
    asm volatile(
        "mma.sync.aligned.m16n8k8.row.col.f32.tf32.tf32.f32 "
        "{%0,%1,%2,%3}, {%4,%5,%6,%7}, {%8,%9}, {%0,%1,%2,%3};\n"
        : "+f"(d[0]), "+f"(d[1]), "+f"(d[2]), "+f"(d[3])
        : "r"(a[0]), "r"(a[1]), "r"(a[2]), "r"(a[3]), "r"(b[0]), "r"(b[1]));
}
__device__ __forceinline__ void cp16(uint32_t saddr, const void* gptr) {
    asm volatile("cp.async.cg.shared.global [%0], [%1], 16;\n"
                 :: "r"(saddr), "l"(gptr));
}
__device__ __forceinline__ void cp_commit() {
    asm volatile("cp.async.commit_group;\n");
}
template <int N>
__device__ __forceinline__ void cp_wait_group() {
    asm volatile("cp.async.wait_group %0;\n" :: "n"(N));
}

// ============================================================================
// Pre-round (merged): blockIdx.y selects among {x, wq, wk, wv, wo}.
// out[i] = tf32_rna(in[i]) stored as fp32 bits (low 13 bits zero).
// ============================================================================
__global__ __launch_bounds__(256) void round_all_kernel(
    const float4* __restrict__ x,  float4* __restrict__ xr,  int n4x,
    const float4* __restrict__ w0, float4* __restrict__ w0r,
    const float4* __restrict__ w1, float4* __restrict__ w1r,
    const float4* __restrict__ w2, float4* __restrict__ w2r,
    const float4* __restrict__ w3, float4* __restrict__ w3r, int n4w)
{
    const float4* in;
    float4* out;
    int n4;
    switch (blockIdx.y) {
        case 0: in = x;  out = xr;  n4 = n4x; break;
        case 1: in = w0; out = w0r; n4 = n4w; break;
        case 2: in = w1; out = w1r; n4 = n4w; break;
        case 3: in = w2; out = w2r; n4 = n4w; break;
        default: in = w3; out = w3r; n4 = n4w; break;
    }
    int stride = gridDim.x * blockDim.x;
    for (int i = blockIdx.x * blockDim.x + threadIdx.x; i < n4; i += stride) {
        float4 v = in[i];
        float4 r;
        r.x = __uint_as_float(f2tf32(v.x));
        r.y = __uint_as_float(f2tf32(v.y));
        r.z = __uint_as_float(f2tf32(v.z));
        r.w = __uint_as_float(f2tf32(v.w));
        out[i] = r;
    }
}

// ============================================================================
// GEMM v4b: Y[M,N] = A[M,K] @ W[N,K]^T, inputs pre-rounded tf32.
// Block tile 128x128x32, 256 threads, warps 2(m) x 4(n), warp tile 64x32.
// __launch_bounds__(256,2) + 110.6KB smem -> 2 CTAs/SM (16 warps).
// THREE-stage cp.async ring: the stage waited on at each barrier was issued
// two compute-blocks earlier, so the wait collapses to barrier cost.
// One cp_commit per iteration (empty at tail) keeps the group count aligned;
// wait_group<1> retires exactly the stage about to be computed.
// blockIdx.z in {0,1,2} selects weight/output (merged QKV launch).
// ============================================================================
#define GM 128
#define GN 128
#define GK 32
#define GS 36   // smem row stride words (36 % 32 == 4 -> frag bank 4g+t, conflict-free)
#define GTILE (GM * GS)                          // 4608 words per tile-buffer
#define NST 3
#define G_SMEM_WORDS (2 * NST * GTILE)           // 27648
#define G_SMEM_BYTES (G_SMEM_WORDS * 4)          // 110592

template <bool ROUND_OUT>
__global__ __launch_bounds__(256, 2) void gemm_v4(
    const float* __restrict__ A,
    const float* __restrict__ W0, const float* __restrict__ W1,
    const float* __restrict__ W2,
    float* __restrict__ Y0, float* __restrict__ Y1, float* __restrict__ Y2)
{
    const float* __restrict__ W = (blockIdx.z == 0) ? W0 : (blockIdx.z == 1 ? W1 : W2);
    float* __restrict__ Y       = (blockIdx.z == 0) ? Y0 : (blockIdx.z == 1 ? Y1 : Y2);

    extern __shared__ uint32_t gsm[];
    uint32_t* sA = gsm;                    // [NST][GTILE]
    uint32_t* sB = gsm + NST * GTILE;      // [NST][GTILE]
    const uint32_t sA_u = (uint32_t)__cvta_generic_to_shared(sA);
    const uint32_t sB_u = (uint32_t)__cvta_generic_to_shared(sB);

    const int tid  = threadIdx.x;
    const int lane = tid & 31;
    const int warp = tid >> 5;
    const int g = lane >> 2, t = lane & 3;
    const int wm = warp >> 2;              // 0..1 -> 64-row slab
    const int wn = warp & 3;               // 0..3 -> 32-col slab
    const int bm0 = blockIdx.y * GM;
    const int bn0 = blockIdx.x * GN;

    const int lr = tid >> 3;               // 0..31 base row
    const int lc = (tid & 7) << 2;         // 0..28

    float acc[4][4][4];
#pragma unroll
    for (int mi = 0; mi < 4; mi++)
#pragma unroll
        for (int ni = 0; ni < 4; ni++)
#pragma unroll
            for (int j = 0; j < 4; j++) acc[mi][ni][j] = 0.f;

    // fill one k-block into stage b: A 1024 chunks, B 1024 chunks (4 each/thr)
    auto fill = [&](int b, int kf) {
        const uint32_t ab = sA_u + (uint32_t)(b * GTILE * 4);
        const uint32_t bb = sB_u + (uint32_t)(b * GTILE * 4);
#pragma unroll
        for (int i = 0; i < 4; i++) {
            int r = lr + i * 32;
            cp16(ab + (uint32_t)((r * GS + lc) * 4),
                 A + (size_t)(bm0 + r) * D_ + kf + lc);
            cp16(bb + (uint32_t)((r * GS + lc) * 4),
                 W + (size_t)(bn0 + r) * D_ + kf + lc);
        }
    };

    // prologue: stages 0 and 1 in flight
    fill(0, 0);
    cp_commit();
    fill(1, GK);
    cp_commit();

    const int NB = D_ / GK;   // 64
    int st = 0;               // stage index of block j
    for (int j = 0; j < NB; j++) {
        cp_wait_group<1>();              // stage of block j landed
        __syncthreads();                 // visible to all; prior compute done

        if (j + 2 < NB) {                // refill the stage freed 1 iter ago
            int sf = st + 2; if (sf >= NST) sf -= NST;
            fill(sf, (j + 2) * GK);
        }
        cp_commit();                     // one group per iter (empty at tail)

        const uint32_t* cA = sA + st * GTILE;
        const uint32_t* cB = sB + st * GTILE;
#pragma unroll
        for (int ks = 0; ks < GK; ks += 8) {
            uint32_t af[4][4], bf[4][2];
#pragma unroll
            for (int mi = 0; mi < 4; mi++) {
                int r0 = wm * 64 + mi * 16;
                af[mi][0] = cA[(r0 + g    ) * GS + ks + t    ];
                af[mi][1] = cA[(r0 + g + 8) * GS + ks + t    ];
                af[mi][2] = cA[(r0 + g    ) * GS + ks + t + 4];
                af[mi][3] = cA[(r0 + g + 8) * GS + ks + t + 4];
            }
#pragma unroll
            for (int ni = 0; ni < 4; ni++) {
                int c0 = wn * 32 + ni * 8;
                bf[ni][0] = cB[(c0 + g) * GS + ks + t    ];
                bf[ni][1] = cB[(c0 + g) * GS + ks + t + 4];
            }
#pragma unroll
            for (int mi = 0; mi < 4; mi++)
#pragma unroll
                for (int ni = 0; ni < 4; ni++)
                    mma_tf32(acc[mi][ni], af[mi], bf[ni]);
        }
        if (++st == NST) st = 0;
    }

    // ---- epilogue ----
#pragma unroll
    for (int mi = 0; mi < 4; mi++)
#pragma unroll
        for (int ni = 0; ni < 4; ni++) {
            int r0 = bm0 + wm * 64 + mi * 16 + g;
            int c0 = bn0 + wn * 32 + ni * 8 + 2 * t;
            float v0 = acc[mi][ni][0], v1 = acc[mi][ni][1];
            float v2 = acc[mi][ni][2], v3 = acc[mi][ni][3];
            if (ROUND_OUT) {
                v0 = __uint_as_float(f2tf32(v0));
                v1 = __uint_as_float(f2tf32(v1));
                v2 = __uint_as_float(f2tf32(v2));
                v3 = __uint_as_float(f2tf32(v3));
            }
            *(float2*)&Y[(size_t)r0 * D_ + c0] = make_float2(v0, v1);
            *(float2*)&Y[(size_t)(r0 + 8) * D_ + c0] = make_float2(v2, v3);
        }
}

// ============================================================================
// Flash attention v2 (R14 passing version, verbatim): cp.async-pipelined K/V.
//   K double-buffered: K[i+1] copies while softmax+PV of tile i run.
//   V single-buffered: V[i] copies while QK of tile i runs.
// smem: Q 128x132 | K 2x 64x132 | V 64x136 | P 128x68 = 204800 B.
// ============================================================================
#define FQ   128
#define FKV  64
#define SQW  132
#define SVW  136
#define SPW  68
#define QOFF 0
#define KOFF (FQ * SQW)                 // 16896
#define KBUF (FKV * SQW)                // 8448
#define VOFF (KOFF + 2 * KBUF)          // 33792
#define POFF (VOFF + FKV * SVW)         // 42496
#define FSMEM_WORDS (POFF + FQ * SPW)   // 51200
#define FSMEM_BYTES (FSMEM_WORDS * 4)   // 204800 B

__global__ __launch_bounds__(256) void flash_tf32(
    const float* __restrict__ Q, const float* __restrict__ Kg,
    const float* __restrict__ Vg, float* __restrict__ O)
{
    extern __shared__ uint32_t sm[];
    const uint32_t sm_u = (uint32_t)__cvta_generic_to_shared(sm);
    const int tid  = threadIdx.x;
    const int lane = tid & 31;
    const int w    = tid >> 5;
    const int g = lane >> 2, t = lane & 3;
    const int qt = blockIdx.x, h = blockIdx.y, b = blockIdx.z;
    const int wr = w * 16;

    const size_t qbase  = ((size_t)(b * S_ + qt * FQ)) * D_ + (size_t)h * HD_;
    const size_t kvbase = ((size_t)b * S_) * D_ + (size_t)h * HD_;

    const int fr = tid >> 5;             // per-thread copy coords: row 0..7 base
    const int fc = (tid & 31) << 2;      // col 0..124

    // issue K[0] into kbuf0 (async), then Q tile (plain copies)
#pragma unroll
    for (int i = 0; i < 8; i++) {
        int r = fr + i * 8;              // 0..63
        cp16(sm_u + (uint32_t)((KOFF + r * SQW + fc) * 4),
             Kg + kvbase + (size_t)r * D_ + fc);
    }
    cp_commit();
#pragma unroll
    for (int i = 0; i < 16; i++) {
        int idx = tid + i * 256;
        int r = idx >> 5;
        int c = (idx & 31) << 2;
        *(uint4*)&sm[QOFF + r * SQW + c] =
            *(const uint4*)(Q + qbase + (size_t)r * D_ + c);
    }

    float o[16][4];
#pragma unroll
    for (int ni = 0; ni < 16; ni++)
#pragma unroll
        for (int j = 0; j < 4; j++) o[ni][j] = 0.f;
    float m0 = -1e30f, m1 = -1e30f, l0 = 0.f, l1 = 0.f;
    const float scale = 0.08838834764831845f;   // 1/sqrt(128)

    cp_wait_group<0>();
    __syncthreads();                      // K[0] + Q visible

    const int NT = S_ / FKV;              // 32 tiles
    for (int it = 0; it < NT; it++) {
        const int kv0 = it * FKV;

        // ---- issue V[it] copy (overlaps QK compute) ----
#pragma unroll
        for (int i = 0; i < 8; i++) {
            int r = fr + i * 8;
            cp16(sm_u + (uint32_t)((VOFF + r * SVW + fc) * 4),
                 Vg + kvbase + (size_t)(kv0 + r) * D_ + fc);
        }
        cp_commit();

        // ---- S = Q @ K^T from kbuf[it&1] ----
        const int kb = KOFF + (it & 1) * KBUF;
        float s[8][4];
#pragma unroll
        for (int ni = 0; ni < 8; ni++)
#pragma unroll
            for (int j = 0; j < 4; j++) s[ni][j] = 0.f;

#pragma unroll
        for (int ks = 0; ks < HD_; ks += 8) {
            uint32_t af[4];
            af[0] = sm[QOFF + (wr + g    ) * SQW + ks + t    ];
            af[1] = sm[QOFF + (wr + g + 8) * SQW + ks + t    ];
            af[2] = sm[QOFF + (wr + g    ) * SQW + ks + t + 4];
            af[3] = sm[QOFF + (wr + g + 8) * SQW + ks + t + 4];
#pragma unroll
            for (int ni = 0; ni < 8; ni++) {
                uint32_t bf[2];
                bf[0] = sm[kb + (ni * 8 + g) * SQW + ks + t    ];
                bf[1] = sm[kb + (ni * 8 + g) * SQW + ks + t + 4];
                mma_tf32(s[ni], af, bf);
            }
        }

        // ---- issue K[it+1] copy (overlaps softmax + PV) ----
        if (it + 1 < NT) {
            const int nb = KOFF + ((it + 1) & 1) * KBUF;
#pragma unroll
            for (int i = 0; i < 8; i++) {
                int r = fr + i * 8;
                cp16(sm_u + (uint32_t)((nb + r * SQW + fc) * 4),
                     Kg + kvbase + (size_t)(kv0 + FKV + r) * D_ + fc);
            }
        }
        cp_commit();
        cp_wait_group<1>();    // all but most-recent group done => V[it] landed
        __syncthreads();

        // ---- online softmax (unchanged numerics) ----
        float mx0 = -1e30f, mx1 = -1e30f;
#pragma unroll
        for (int ni = 0; ni < 8; ni++) {
#pragma unroll
            for (int j = 0; j < 4; j++) s[ni][j] *= scale;
            mx0 = fmaxf(mx0, fmaxf(s[ni][0], s[ni][1]));
            mx1 = fmaxf(mx1, fmaxf(s[ni][2], s[ni][3]));
        }
        mx0 = fmaxf(mx0, __shfl_xor_sync(0xffffffffu, mx0, 1));
        mx0 = fmaxf(mx0, __shfl_xor_sync(0xffffffffu, mx0, 2));
        mx1 = fmaxf(mx1, __shfl_xor_sync(0xffffffffu, mx1, 1));
        mx1 = fmaxf(mx1, __shfl_xor_sync(0xffffffffu, mx1, 2));
        float mn0 = fmaxf(m0, mx0), mn1 = fmaxf(m1, mx1);
        float a0 = __expf(m0 - mn0), a1 = __expf(m1 - mn1);
        m0 = mn0; m1 = mn1;

        float r0 = 0.f, r1 = 0.f;
#pragma unroll
        for (int ni = 0; ni < 8; ni++) {
            float p0 = __expf(s[ni][0] - mn0);
            float p1 = __expf(s[ni][1] - mn0);
            float p2 = __expf(s[ni][2] - mn1);
            float p3 = __expf(s[ni][3] - mn1);
            r0 += p0 + p1; r1 += p2 + p3;
            uint2 u01 = make_uint2(f2tf32(p0), f2tf32(p1));
            uint2 u23 = make_uint2(f2tf32(p2), f2tf32(p3));
            *(uint2*)&sm[POFF + (wr + g    ) * SPW + ni * 8 + 2 * t] = u01;
            *(uint2*)&sm[POFF + (wr + g + 8) * SPW + ni * 8 + 2 * t] = u23;
        }
        r0 += __shfl_xor_sync(0xffffffffu, r0, 1);
        r0 += __shfl_xor_sync(0xffffffffu, r0, 2);
        r1 += __shfl_xor_sync(0xffffffffu, r1, 1);
        r1 += __shfl_xor_sync(0xffffffffu, r1, 2);
        l0 = l0 * a0 + r0;
        l1 = l1 * a1 + r1;
#pragma unroll
        for (int ni = 0; ni < 16; ni++) {
            o[ni][0] *= a0; o[ni][1] *= a0; o[ni][2] *= a1; o[ni][3] *= a1;
        }
        __syncwarp();   // P region is warp-private

        // ---- O += P @ V ----
#pragma unroll
        for (int ks = 0; ks < FKV; ks += 8) {
            uint32_t af[4];
            af[0] = sm[POFF + (wr + g    ) * SPW + ks + t    ];
            af[1] = sm[POFF + (wr + g + 8) * SPW + ks + t    ];
            af[2] = sm[POFF + (wr + g    ) * SPW + ks + t + 4];
            af[3] = sm[POFF + (wr + g + 8) * SPW + ks + t + 4];
#pragma unroll
            for (int ni = 0; ni < 16; ni++) {
                uint32_t bf[2];
                bf[0] = sm[VOFF + (ks + t    ) * SVW + ni * 8 + g];
                bf[1] = sm[VOFF + (ks + t + 4) * SVW + ni * 8 + g];
                mma_tf32(o[ni], af, bf);
            }
        }

        cp_wait_group<0>();    // K[it+1] landed
        __syncthreads();       // V reads done before next V overwrite
    }

    // epilogue: normalize + tf32-round (GEMM2 consumes raw)
    float i0 = 1.0f / l0;
    float i1 = 1.0f / l1;
#pragma unroll
    for (int ni = 0; ni < 16; ni++) {
        int c0 = ni * 8 + 2 * t;
        *(float2*)&O[qbase + (size_t)(wr + g) * D_ + c0] = make_float2(
            __uint_as_float(f2tf32(o[ni][0] * i0)),
            __uint_as_float(f2tf32(o[ni][1] * i0)));
        *(float2*)&O[qbase + (size_t)(wr + g + 8) * D_ + c0] = make_float2(
            __uint_as_float(f2tf32(o[ni][2] * i1)),
            __uint_as_float(f2tf32(o[ni][3] * i1)));
    }
}

// ============================================================================
// Launch: pre-round (merged), merged q/k/v projections, flash, out projection
// ============================================================================
extern "C" void kernel_launch(void* const* d_in, const int* in_sizes, int n_in,
                              void* d_out, int out_size) {
    const float* x  = (const float*)d_in[0];
    const float* wq = (const float*)d_in[1];
    const float* wk = (const float*)d_in[2];
    const float* wv = (const float*)d_in[3];
    const float* wo = (const float*)d_in[4];
    float* out = (float*)d_out;

    float *qb, *kb, *vb, *cb, *xr, *wqr, *wkr, *wvr, *wor;
    cudaGetSymbolAddress((void**)&qb, g_q);
    cudaGetSymbolAddress((void**)&kb, g_k);
    cudaGetSymbolAddress((void**)&vb, g_v);
    cudaGetSymbolAddress((void**)&cb, g_ctx);
    cudaGetSymbolAddress((void**)&xr, g_xr);
    cudaGetSymbolAddress((void**)&wqr, g_wqr);
    cudaGetSymbolAddress((void**)&wkr, g_wkr);
    cudaGetSymbolAddress((void**)&wvr, g_wvr);
    cudaGetSymbolAddress((void**)&wor, g_wor);

    cudaFuncSetAttribute(gemm_v4<true>,
                         cudaFuncAttributeMaxDynamicSharedMemorySize, G_SMEM_BYTES);
    cudaFuncSetAttribute(gemm_v4<false>,
                         cudaFuncAttributeMaxDynamicSharedMemorySize, G_SMEM_BYTES);
    cudaFuncSetAttribute(flash_tf32,
                         cudaFuncAttributeMaxDynamicSharedMemorySize, FSMEM_BYTES);

    // ---- pre-round inputs to tf32 (merged single launch) ----
    const int n4x = (MTOK * D_) / 4;   // 4M float4
    const int n4w = (D_ * D_) / 4;     // 1M float4
    dim3 rg(296, 5);                    // 2 blocks/SM per segment
    round_all_kernel<<<rg, 256>>>(
        (const float4*)x,  (float4*)xr,  n4x,
        (const float4*)wq, (float4*)wqr,
        (const float4*)wk, (float4*)wkr,
        (const float4*)wv, (float4*)wvr,
        (const float4*)wo, (float4*)wor, n4w);

    // ---- q/k/v projections (merged), outputs tf32-rounded ----
    dim3 gqkv(D_ / GN, MTOK / GM, 3);   // (16, 32, 3)
    gemm_v4<true><<<gqkv, 256, G_SMEM_BYTES>>>(xr, wqr, wkr, wvr, qb, kb, vb);

    // ---- attention (ctx written tf32-rounded) ----
    flash_tf32<<<dim3(S_ / FQ, H_, B_), 256, FSMEM_BYTES>>>(qb, kb, vb, cb);

    // ---- output projection, unrounded final result ----
    dim3 go(D_ / GN, MTOK / GM, 1);     // (16, 32, 1)
    gemm_v4<false><<<go, 256, G_SMEM_BYTES>>>(cb, wor, wor, wor, out, out, out);
}